// round 14
// baseline (speedup 1.0000x reference)
#include <cuda_runtime.h>
#include <cuda_fp16.h>
#include <math.h>

#define NN    32768
#define EE    262144
#define HID   64
#define HEADS 4
#define CC    64
#define HC    256
#define EDIM  3

// ---------------- scratch ----------------
// g_xh layout: per node, 32 colpairs x 4 heads x half2  => uint4 per colpair
__device__ __align__(16) __half  g_xh[(size_t)NN * HC];
__device__ __align__(16) __half  g_zh[(size_t)NN * HID];   // fp16 gemm input
__device__ uint2   g_wb[2 * 4096];             // prepacked B fragments, both layers
__device__ float   g_as[NN * HEADS];
__device__ float   g_ad[NN * HEADS];
__device__ float   g_ex[(size_t)EE * HEADS];   // exp(logit)
__device__ float   g_denom[NN * HEADS];
__device__ float   g_rdn[NN * HEADS];          // 0.25 / (denom + eps)
__device__ float   g_accum[(size_t)NN * CC];
__device__ float   g_z[(size_t)NN * HID];      // fp32 dump for layer-0 fin output
__device__ float   g_v[2 * EDIM * HEADS];

// ---------------- f32x2 helpers ----------------
__device__ __forceinline__ unsigned long long splat2(float x) {
    unsigned long long r; unsigned u = __float_as_uint(x);
    asm("mov.b64 %0, {%1, %2};" : "=l"(r) : "r"(u), "r"(u));
    return r;
}
__device__ __forceinline__ void ffma2(unsigned long long& d, unsigned long long a, unsigned long long b) {
    asm("fma.rn.f32x2 %0, %1, %2, %3;" : "=l"(d) : "l"(a), "l"(b), "l"(d));
}
__device__ __forceinline__ void unpack2(unsigned long long v, float& lo, float& hi) {
    unsigned a, b;
    asm("mov.b64 {%0, %1}, %2;" : "=r"(a), "=r"(b) : "l"(v));
    lo = __uint_as_float(a); hi = __uint_as_float(b);
}
__device__ __forceinline__ unsigned long long pack2(float lo, float hi) {
    unsigned long long r;
    asm("mov.b64 %0, {%1, %2};" : "=l"(r) : "r"(__float_as_uint(lo)), "r"(__float_as_uint(hi)));
    return r;
}
__device__ __forceinline__ void red_v4(float* p, float a, float b, float c, float d) {
    asm volatile("red.global.add.v4.f32 [%0], {%1, %2, %3, %4};"
                 :: "l"(p), "f"(a), "f"(b), "f"(c), "f"(d) : "memory");
}

// ---------------- init: zero accum/denom, h->fp16, pack W fragments, g_v ----------------
__global__ void k_init(const float* __restrict__ h,
                       const float* __restrict__ W1, const float* __restrict__ W2,
                       const float* __restrict__ We1, const float* __restrict__ ae1,
                       const float* __restrict__ We2, const float* __restrict__ ae2)
{
    int i = blockIdx.x * 256 + threadIdx.x;    // grid covers NN*CC
    g_accum[i] = 0.0f;
    if (i < NN * HEADS) g_denom[i] = 0.0f;
    if (i < NN * HID) g_zh[i] = __float2half(h[i]);
    if (i < 2 * 4096) {
        // B-fragment pack for mma.m16n8k16 (row.col):
        // frag idx: L, j (n8 tile 0..31), kk (k16 step 0..3), lane
        int L = i >> 12;
        int idx = i & 4095;
        int lane = idx & 31;
        int kk = (idx >> 5) & 3;
        int j = idx >> 7;
        int n = 8 * j + (lane >> 2);
        int k0 = kk * 16 + (lane & 3) * 2;
        const float* Wp = L ? W2 : W1;
        __half2 lo = __floats2half2_rn(Wp[k0 * HC + n],       Wp[(k0 + 1) * HC + n]);
        __half2 hi = __floats2half2_rn(Wp[(k0 + 8) * HC + n], Wp[(k0 + 9) * HC + n]);
        g_wb[i] = make_uint2(*(unsigned*)&lo, *(unsigned*)&hi);
    }
    if (blockIdx.x == 0 && threadIdx.x < 2 * EDIM * HEADS) {
        int t = threadIdx.x;
        int L = t / (EDIM * HEADS);
        int r = t % (EDIM * HEADS);
        int d = r / HEADS, hh = r % HEADS;
        const float* We = L ? We2 : We1;
        const float* ae = L ? ae2 : ae1;
        float s = 0.f;
        for (int c = 0; c < CC; c++) s += We[d * HC + hh * CC + c] * ae[hh * CC + c];
        g_v[t] = s;
    }
}

// ---------------- tensor-core GEMM: x = zh @ W (fp16 MMA, fp32 acc) ----------------
// 256 thr = 8 warps; warp: 16 rows x 256 cols; CTA: 128 rows; grid 256
// smem stage: 128 rows x 132 words (uint = half2), final uint4 transposed store
__global__ void __launch_bounds__(256) k_gemm(
    int L, const float* __restrict__ a_src, const float* __restrict__ a_dst)
{
    extern __shared__ unsigned sx[];           // 128 * 132 words
    int tid = threadIdx.x;
    int wid = tid >> 5, lane = tid & 31;
    int q = lane & 3, rquad = lane >> 2;
    int rows0 = blockIdx.x * 128 + wid * 16;
    size_t r_lo = rows0 + rquad;

    const uint2* wb = g_wb + L * 4096;

    // A fragments for 4 k-steps (row.col m16n8k16 layout)
    unsigned a[4][4];
    #pragma unroll
    for (int kk = 0; kk < 4; kk++) {
        int c = kk * 16 + q * 2;
        a[kk][0] = *(const unsigned*)(g_zh + r_lo * 64 + c);
        a[kk][1] = *(const unsigned*)(g_zh + (r_lo + 8) * 64 + c);
        a[kk][2] = *(const unsigned*)(g_zh + r_lo * 64 + c + 8);
        a[kk][3] = *(const unsigned*)(g_zh + (r_lo + 8) * 64 + c + 8);
    }

    float ps_lo[4] = {0,0,0,0}, ps_hi[4] = {0,0,0,0};
    float pd_lo[4] = {0,0,0,0}, pd_hi[4] = {0,0,0,0};

    int nl = wid * 16 + rquad;
    #pragma unroll 4
    for (int j = 0; j < 32; j++) {
        float c0 = 0.f, c1 = 0.f, c2 = 0.f, c3 = 0.f;
        #pragma unroll
        for (int kk = 0; kk < 4; kk++) {
            uint2 b = wb[(j * 4 + kk) * 32 + lane];
            asm volatile(
                "mma.sync.aligned.m16n8k16.row.col.f32.f16.f16.f32 "
                "{%0,%1,%2,%3}, {%4,%5,%6,%7}, {%8,%9}, {%0,%1,%2,%3};"
                : "+f"(c0), "+f"(c1), "+f"(c2), "+f"(c3)
                : "r"(a[kk][0]), "r"(a[kk][1]), "r"(a[kk][2]), "r"(a[kk][3]),
                  "r"(b.x), "r"(b.y));
        }
        int g = j >> 3;
        int cpw = (j & 7) * 4 + q;                   // colpair within head, 0..31
        float2 as2 = ((const float2*)a_src)[g * 32 + cpw];
        float2 ad2 = ((const float2*)a_dst)[g * 32 + cpw];
        ps_lo[g] += c0 * as2.x + c1 * as2.y;  ps_hi[g] += c2 * as2.x + c3 * as2.y;
        pd_lo[g] += c0 * ad2.x + c1 * ad2.y;  pd_hi[g] += c2 * ad2.x + c3 * ad2.y;
        __half2 hlo = __floats2half2_rn(c0, c1);
        __half2 hhi = __floats2half2_rn(c2, c3);
        int widx = cpw * 4 + g;                      // word within node row, 0..127
        sx[nl * 132 + widx]       = *(unsigned*)&hlo;
        sx[(nl + 8) * 132 + widx] = *(unsigned*)&hhi;
    }

    // reduce alpha dots across the quad (lanes sharing a row)
    #pragma unroll
    for (int g = 0; g < 4; g++) {
        #pragma unroll
        for (int off = 1; off <= 2; off <<= 1) {
            ps_lo[g] += __shfl_xor_sync(0xFFFFFFFFu, ps_lo[g], off);
            ps_hi[g] += __shfl_xor_sync(0xFFFFFFFFu, ps_hi[g], off);
            pd_lo[g] += __shfl_xor_sync(0xFFFFFFFFu, pd_lo[g], off);
            pd_hi[g] += __shfl_xor_sync(0xFFFFFFFFu, pd_hi[g], off);
        }
    }
    if (q == 0) {
        ((float4*)g_as)[r_lo]     = make_float4(ps_lo[0], ps_lo[1], ps_lo[2], ps_lo[3]);
        ((float4*)g_as)[r_lo + 8] = make_float4(ps_hi[0], ps_hi[1], ps_hi[2], ps_hi[3]);
        ((float4*)g_ad)[r_lo]     = make_float4(pd_lo[0], pd_lo[1], pd_lo[2], pd_lo[3]);
        ((float4*)g_ad)[r_lo + 8] = make_float4(pd_hi[0], pd_hi[1], pd_hi[2], pd_hi[3]);
    }

    __syncthreads();

    // coalesced uint4 store of the transposed x tile
    #pragma unroll
    for (int i = 0; i < 16; i++) {
        int u = tid + i * 256;                 // 4096 uint4 per CTA
        int node_l = u >> 5, qq = u & 31;
        uint4 val = *(const uint4*)&sx[node_l * 132 + qq * 4];
        ((uint4*)(g_xh + ((size_t)(blockIdx.x * 128 + node_l)) * HC))[qq] = val;
    }
}

// ---------------- fused edge pass: logit -> exp -> denom, 4 edges/thread ----------------
__global__ void __launch_bounds__(256) k_edge(
    const int* __restrict__ src, const int* __restrict__ dst,
    const float* __restrict__ ea, int L)
{
    int t = blockIdx.x * 256 + threadIdx.x;    // EE/4 threads
    const float* v = g_v + L * EDIM * HEADS;
    float vr[12];
    #pragma unroll
    for (int i = 0; i < 12; i++) vr[i] = v[i];

    int4 s4 = ((const int4*)src)[t];
    int4 d4 = ((const int4*)dst)[t];
    float4 ga = ((const float4*)ea)[t * 3 + 0];
    float4 gb = ((const float4*)ea)[t * 3 + 1];
    float4 gc = ((const float4*)ea)[t * 3 + 2];

    int ss[4] = { s4.x, s4.y, s4.z, s4.w };
    int dd[4] = { d4.x, d4.y, d4.z, d4.w };
    float e0[4] = { ga.x, ga.w, gb.z, gc.y };
    float e1[4] = { ga.y, gb.x, gb.w, gc.z };
    float e2[4] = { ga.z, gb.y, gc.x, gc.w };

    float4 as4[4], ad4[4];
    #pragma unroll
    for (int j = 0; j < 4; j++) {
        as4[j] = ((const float4*)g_as)[ss[j]];
        ad4[j] = ((const float4*)g_ad)[dd[j]];
    }

    #pragma unroll
    for (int j = 0; j < 4; j++) {
        float x0 = as4[j].x + ad4[j].x + e0[j] * vr[0] + e1[j] * vr[4] + e2[j] * vr[8];
        float x1 = as4[j].y + ad4[j].y + e0[j] * vr[1] + e1[j] * vr[5] + e2[j] * vr[9];
        float x2 = as4[j].z + ad4[j].z + e0[j] * vr[2] + e1[j] * vr[6] + e2[j] * vr[10];
        float x3 = as4[j].w + ad4[j].w + e0[j] * vr[3] + e1[j] * vr[7] + e2[j] * vr[11];
        x0 = (x0 > 0.f) ? x0 : 0.2f * x0;
        x1 = (x1 > 0.f) ? x1 : 0.2f * x1;
        x2 = (x2 > 0.f) ? x2 : 0.2f * x2;
        x3 = (x3 > 0.f) ? x3 : 0.2f * x3;
        float ex0 = __expf(x0), ex1 = __expf(x1), ex2 = __expf(x2), ex3 = __expf(x3);
        ((float4*)g_ex)[t * 4 + j] = make_float4(ex0, ex1, ex2, ex3);
        red_v4(&g_denom[dd[j] * 4], ex0, ex1, ex2, ex3);
    }
}

// ---------------- reciprocal denom, vectorized (head-mean 0.25 folded in) ----------------
__global__ void k_rcp() {
    int i = blockIdx.x * 256 + threadIdx.x;   // NN*HEADS/4 threads
    float4 dn = ((const float4*)g_denom)[i];
    float4 rd;
    rd.x = 0.25f * __fdividef(1.0f, dn.x + 1e-16f);
    rd.y = 0.25f * __fdividef(1.0f, dn.y + 1e-16f);
    rd.z = 0.25f * __fdividef(1.0f, dn.z + 1e-16f);
    rd.w = 0.25f * __fdividef(1.0f, dn.w + 1e-16f);
    ((float4*)g_rdn)[i] = rd;
    ((float4*)g_denom)[i] = make_float4(0.f, 0.f, 0.f, 0.f);
}

// ---------------- message: 2 edges/warp, 16 lanes/edge, red.v4 ----------------
__global__ void k_msg(const int* __restrict__ src, const int* __restrict__ dst) {
    int t = blockIdx.x * 256 + threadIdx.x;
    int lane = threadIdx.x & 31;
    int e = ((t >> 5) << 1) + (lane >> 4);
    int r = lane & 15;
    int s = src[e], d = dst[e];
    float4 ex4 = ((const float4*)g_ex)[e];
    float4 rd4 = ((const float4*)g_rdn)[d];
    float al0 = ex4.x * rd4.x;
    float al1 = ex4.y * rd4.y;
    float al2 = ex4.z * rd4.z;
    float al3 = ex4.w * rd4.w;

    const uint4* xr = (const uint4*)(g_xh + (size_t)s * HC);
    uint4 a = xr[2 * r];
    uint4 b = xr[2 * r + 1];

    unsigned long long A0 = splat2(al0), A1 = splat2(al1), A2 = splat2(al2), A3 = splat2(al3);

    float2 f; unsigned long long pa = 0ull, pb = 0ull;
    f = __half22float2(*(__half2*)&a.x); ffma2(pa, A0, pack2(f.x, f.y));
    f = __half22float2(*(__half2*)&a.y); ffma2(pa, A1, pack2(f.x, f.y));
    f = __half22float2(*(__half2*)&a.z); ffma2(pa, A2, pack2(f.x, f.y));
    f = __half22float2(*(__half2*)&a.w); ffma2(pa, A3, pack2(f.x, f.y));
    f = __half22float2(*(__half2*)&b.x); ffma2(pb, A0, pack2(f.x, f.y));
    f = __half22float2(*(__half2*)&b.y); ffma2(pb, A1, pack2(f.x, f.y));
    f = __half22float2(*(__half2*)&b.z); ffma2(pb, A2, pack2(f.x, f.y));
    f = __half22float2(*(__half2*)&b.w); ffma2(pb, A3, pack2(f.x, f.y));

    float m0, m1, m2, m3;
    unpack2(pa, m0, m1);
    unpack2(pb, m2, m3);
    red_v4(&g_accum[d * 64 + 4 * r], m0, m1, m2, m3);
}

// ---------------- bias + layernorm + silu; fp32 out + fp16 zh; zero accum ----------------
__global__ void k_fin(const float* __restrict__ b, const float* __restrict__ lg,
                      const float* __restrict__ lb, float* __restrict__ out)
{
    int n = (blockIdx.x * 256 + threadIdx.x) >> 5;
    int l = threadIdx.x & 31;                  // lane owns cols 2l, 2l+1
    float2 va = ((float2*)g_accum)[n * 32 + l];
    ((float2*)g_accum)[n * 32 + l] = make_float2(0.f, 0.f);
    float2 b2 = ((const float2*)b)[l];
    float v0 = va.x + b2.x, v1 = va.y + b2.y;
    float s = v0 + v1;
    #pragma unroll
    for (int off = 16; off; off >>= 1) s += __shfl_xor_sync(0xFFFFFFFFu, s, off);
    float mu = s * (1.0f / 64.0f);
    float q = (v0 - mu) * (v0 - mu) + (v1 - mu) * (v1 - mu);
    #pragma unroll
    for (int off = 16; off; off >>= 1) q += __shfl_xor_sync(0xFFFFFFFFu, q, off);
    float r = rsqrtf(q * (1.0f / 64.0f) + 1e-5f);
    float2 g2 = ((const float2*)lg)[l];
    float2 t2 = ((const float2*)lb)[l];
    float y0 = (v0 - mu) * r * g2.x + t2.x;
    float y1 = (v1 - mu) * r * g2.y + t2.y;
    y0 = y0 * __fdividef(1.0f, 1.0f + __expf(-y0));
    y1 = y1 * __fdividef(1.0f, 1.0f + __expf(-y1));
    ((float2*)out)[n * 32 + l] = make_float2(y0, y1);
    ((__half2*)g_zh)[n * 32 + l] = __floats2half2_rn(y0, y1);
}

// ---------------- launch ----------------
extern "C" void kernel_launch(void* const* d_in, const int* in_sizes, int n_in,
                              void* d_out, int out_size)
{
    const float* h   = (const float*)d_in[1];
    const int*   ei  = (const int*)d_in[2];
    const float* ea  = (const float*)d_in[3];
    const int*   src = ei;
    const int*   dst = ei + EE;

    const float* W[2]   = { (const float*)d_in[4],  (const float*)d_in[12] };
    const float* We[2]  = { (const float*)d_in[5],  (const float*)d_in[13] };
    const float* asr[2] = { (const float*)d_in[6],  (const float*)d_in[14] };
    const float* ads[2] = { (const float*)d_in[7],  (const float*)d_in[15] };
    const float* aeg[2] = { (const float*)d_in[8],  (const float*)d_in[16] };
    const float* bb[2]  = { (const float*)d_in[9],  (const float*)d_in[17] };
    const float* lng[2] = { (const float*)d_in[10], (const float*)d_in[18] };
    const float* lnb[2] = { (const float*)d_in[11], (const float*)d_in[19] };

    const int smem = 128 * 132 * (int)sizeof(unsigned);   // 67584 B
    cudaFuncSetAttribute(k_gemm, cudaFuncAttributeMaxDynamicSharedMemorySize, smem);

    float* zbuf = nullptr;
    cudaGetSymbolAddress((void**)&zbuf, g_z);

    k_init<<< NN * CC / 256, 256 >>>(h, W[0], W[1], We[0], aeg[0], We[1], aeg[1]);

    for (int L = 0; L < 2; L++) {
        float* zout = (L == 0) ? zbuf : (float*)d_out;
        k_gemm<<< NN / 128, 256, smem >>>(L, asr[L], ads[L]);
        k_edge<<< EE / 1024, 256 >>>(src, dst, ea, L);
        k_rcp <<< NN * HEADS / 1024, 256 >>>();
        k_msg <<< EE / 16, 256 >>>(src, dst);
        k_fin <<< NN / 8, 256 >>>(bb[L], lng[L], lnb[L], zout);
    }
}